// round 14
// baseline (speedup 1.0000x reference)
#include <cuda_runtime.h>
#include <cuda_bf16.h>
#include <math.h>

#define NIMG 16
#define KTOP 5000
#define NSLOT 5120          // padded to 512*10
#define BND_CAP 32768
#define TIE_CAP 512
#define NSORT 8192
#define SEL_BINS 16384
#define SEL_T 1024
#define FULL_T 512
#define FULL_E 10
#define MAXFIDX 4423679u

// libdevice precise exp (immune to -use_fast_math substitution)
extern "C" __device__ float __nv_expf(float);

// ---------------- device scratch (static, zero-initialized, no runtime alloc) ----------------
__device__ int   g_hist[NIMG][4096];
__device__ int   g_bucket[NIMG];
__device__ int   g_cntAbove[NIMG];
__device__ int   g_selCnt[NIMG];
__device__ int   g_bndCnt[NIMG];
__device__ int   g_fb;                      // selection fallback flag
__device__ unsigned long long g_sel[NIMG][KTOP];
__device__ unsigned long long g_bnd[NIMG][BND_CAP];

__device__ float g_x1[NIMG][NSLOT];
__device__ float g_y1[NIMG][NSLOT];
__device__ float g_x2[NIMG][NSLOT];
__device__ float g_y2[NIMG][NSLOT];
__device__ float g_sc[NIMG][NSLOT];
__device__ float g_cl[NIMG][NSLOT];

struct Levels {
    const float* cls[5];
    int n4[5];      // float4 per image
    int hwlog[5];
    int aoff[5];
};
struct BoxPtrs { const float* p[5]; };

// order-preserving float -> uint key (ascending)
__device__ __forceinline__ unsigned f2k(float f) {
    unsigned u = __float_as_uint(f);
    return (u & 0x80000000u) ? ~u : (u | 0x80000000u);
}
__device__ __forceinline__ float k2f(unsigned k) {
    return (k & 0x80000000u) ? __uint_as_float(k & 0x7FFFFFFFu) : __uint_as_float(~k);
}
__device__ __forceinline__ unsigned long long umax64(unsigned long long a, unsigned long long b) {
    return a > b ? a : b;
}
__device__ __forceinline__ float sigmoid_rn(float v) {
    return __fdiv_rn(1.0f, __fadd_rn(1.0f, __nv_expf(-v)));
}
// monotone (non-decreasing) 14-bit bin over candidate keys
__device__ __forceinline__ unsigned selbin(unsigned kk) {
    if (kk < 0xC0200000u) return 0u;
    unsigned d = (kk - 0xC0200000u) >> 14;
    return d > (SEL_BINS - 1) ? (SEL_BINS - 1) : d;
}

#define THRESH 2.6f

// ---------------- L0: fused single sweep — compact everything >= THRESH ----------------
__global__ void k_sweep(Levels lv) {
    // reset flags for this replay (previous replay's consumers all finished)
    if (blockIdx.x == 0 && blockIdx.y == 0 && blockIdx.z == 0 && threadIdx.x == 0) g_fb = 0;
    int L = blockIdx.z;
    int n4 = lv.n4[L];
    int b = blockIdx.y;
    const float4* p = ((const float4*)lv.cls[L]) + (size_t)b * (size_t)n4;
    int hwlog = lv.hwlog[L];
    int hwmask = (1 << hwlog) - 1;
    int aoff = lv.aoff[L];
    int stride = gridDim.x * blockDim.x;
    for (int i = blockIdx.x * blockDim.x + threadIdx.x; i < n4; i += stride) {
        float4 v = p[i];
        float mx = fmaxf(fmaxf(v.x, v.y), fmaxf(v.z, v.w));
        if (mx >= THRESH) {
            float vv[4] = { v.x, v.y, v.z, v.w };
#pragma unroll
            for (int j = 0; j < 4; j++) {
                if (vv[j] >= THRESH) {
                    int e = i * 4 + j;
                    int ch = e >> hwlog;
                    int pix = e & hwmask;
                    int a = ch / 90;
                    int c = ch - a * 90;
                    int n = aoff + pix * 9 + a;
                    unsigned fidx = (unsigned)(n * 90 + c);
                    unsigned long long rec = ((unsigned long long)f2k(vv[j]) << 32) | fidx;
                    int pos = atomicAdd(&g_bndCnt[b], 1);
                    if (pos < BND_CAP) g_bnd[b][pos] = rec;
                }
            }
        }
    }
}

// ---------------- L1: exact rank-ordered top-KTOP from candidates ----------------
// Produces g_sel in EXACT jax.lax.top_k order (key desc, flat index asc) without a sort:
// histogram -> parallel suffix scan -> scatter at topPrefix[bin]+cursor -> per-bin fixup.
__global__ void __launch_bounds__(SEL_T, 1) k_selectA() {
    extern __shared__ int sh[];                // h[SEL_BINS] | pfx[SEL_BINS]
    int* h = sh;
    int* pfx = sh + SEL_BINS;
    __shared__ unsigned long long tl[TIE_CAP];
    __shared__ int s_f, s_above, s_tcnt;
    __shared__ int wsum[32];

    int b = blockIdx.x, t = threadIdx.x;
    int n = g_bndCnt[b];
    if (n < KTOP || n > BND_CAP) {             // speculation failed for this image
        if (t == 0) atomicExch(&g_fb, 1);
        return;
    }
    if (t == 0) s_tcnt = 0;

    for (int i = t; i < SEL_BINS; i += SEL_T) h[i] = 0;
    __syncthreads();
    for (int i = t; i < n; i += SEL_T) {
        unsigned kk = (unsigned)(g_bnd[b][i] >> 32);
        atomicAdd(&h[selbin(kk)], 1);
    }
    __syncthreads();

    // per-thread segment of 16 bins; block suffix-scan (sum over HIGHER bins)
    const int SPT = SEL_BINS / SEL_T;          // 16
    int base = t * SPT;
    int hv[SPT];
    int seg = 0;
#pragma unroll
    for (int j = 0; j < SPT; j++) { hv[j] = h[base + j]; seg += hv[j]; }
    int lane = t & 31, wid = t >> 5;
    int incl = seg;
#pragma unroll
    for (int o = 1; o < 32; o <<= 1) { int x = __shfl_up_sync(~0u, incl, o); if (lane >= o) incl += x; }
    if (lane == 31) wsum[wid] = incl;
    __syncthreads();
    if (wid == 0) {
        int v = wsum[lane];
#pragma unroll
        for (int o = 1; o < 32; o <<= 1) { int x = __shfl_up_sync(~0u, v, o); if (lane >= o) v += x; }
        wsum[lane] = v;
    }
    __syncthreads();
    int P = incl - seg + (wid ? wsum[wid - 1] : 0);   // exclusive prefix over threads
    int total = wsum[31];
    int suffix = total - P - seg;                     // sum over threads > t (higher bins)
    int run = suffix;
    int tp[SPT];
#pragma unroll
    for (int j = SPT - 1; j >= 0; j--) { tp[j] = run; run += hv[j]; }
#pragma unroll
    for (int j = 0; j < SPT; j++) {
        pfx[base + j] = tp[j];                        // scatter cursor init
        if (tp[j] < KTOP && tp[j] + hv[j] >= KTOP) { s_f = base + j; s_above = tp[j]; }
    }
    __syncthreads();
    int f = s_f, above = s_above;

    // scatter: bins above threshold go straight to their rank block; threshold bin -> tie list
    for (int i = t; i < n; i += SEL_T) {
        unsigned long long rec = g_bnd[b][i];
        int bin = (int)selbin((unsigned)(rec >> 32));
        if (bin > f) {
            int p = atomicAdd(&pfx[bin], 1);
            g_sel[b][p] = rec;
        } else if (bin == f) {
            int p = atomicAdd(&s_tcnt, 1);
            if (p < TIE_CAP) tl[p] = rec;
        }
    }
    __syncthreads();
    int m = s_tcnt;
    if (m > TIE_CAP) {
        if (t == 0) atomicExch(&g_fb, 1);
        return;
    }
    int need = KTOP - above;
    for (int i = t; i < m; i += SEL_T) {
        unsigned long long ri = tl[i];
        unsigned ki = (unsigned)(ri >> 32);
        unsigned xi = (unsigned)ri;
        int rank = 0;
        for (int j = 0; j < m; j++) {
            unsigned long long rj = tl[j];
            unsigned kj = (unsigned)(rj >> 32);
            unsigned xj = (unsigned)rj;
            rank += (kj > ki) || (kj == ki && xj < xi);
        }
        if (rank < need) g_sel[b][above + rank] = ri;
    }
    __syncthreads();

    // fixup: bins above threshold with >1 record need within-bin ordering (key desc, fidx asc)
#pragma unroll
    for (int j = 0; j < SPT; j++) {
        int bin = base + j;
        if (bin > f) {
            int cnt = hv[j];
            if (cnt > 1) {
                if (cnt > 32) { atomicExch(&g_fb, 1); continue; }
                int st = pfx[bin] - cnt;
                unsigned long long v[32];
                for (int q = 0; q < cnt; q++) {
                    unsigned long long r = g_sel[b][st + q];
                    v[q] = (r & 0xFFFFFFFF00000000ull) | (unsigned long long)(0xFFFFFFFFu - (unsigned)r);
                }
                for (int a = 1; a < cnt; a++) {
                    unsigned long long x = v[a];
                    int c = a - 1;
                    while (c >= 0 && v[c] < x) { v[c + 1] = v[c]; c--; }
                    v[c + 1] = x;
                }
                for (int q = 0; q < cnt; q++) {
                    unsigned long long x = v[q];
                    g_sel[b][st + q] = (x & 0xFFFFFFFF00000000ull) | (unsigned long long)(0xFFFFFFFFu - (unsigned)x);
                }
            }
        }
    }
}

// ---------------- L2: decode (parallel, garbage-safe when speculation failed) ----------------
__global__ void k_decode(BoxPtrs bp, const float* __restrict__ anchors) {
    int b = blockIdx.y;
    int k = blockIdx.x * blockDim.x + threadIdx.x;
    if (k >= NSLOT) return;
    if (k >= KTOP) {
        g_x1[b][k] = 0.f; g_y1[b][k] = 0.f; g_x2[b][k] = 0.f; g_y2[b][k] = 0.f;
        g_sc[b][k] = -1.f; g_cl[b][k] = 0.f;
        return;
    }
    unsigned long long rec = g_sel[b][k];
    unsigned key = (unsigned)(rec >> 32);
    unsigned fidx = (unsigned)rec;
    if (fidx > MAXFIDX) fidx = 0;              // safety on speculative-garbage path
    float v = k2f(key);
    float score = sigmoid_rn(v);

    int n = (int)(fidx / 90u);
    int c = (int)(fidx - (unsigned)n * 90u);

    int L, aoff, HW;
    if      (n < 36864) { L = 0; aoff = 0;     HW = 4096; }
    else if (n < 46080) { L = 1; aoff = 36864; HW = 1024; }
    else if (n < 48384) { L = 2; aoff = 46080; HW = 256;  }
    else if (n < 48960) { L = 3; aoff = 48384; HW = 64;   }
    else                { L = 4; aoff = 48960; HW = 16;   }
    int r = n - aoff;
    int pix = r / 9;
    int a = r - pix * 9;

    const float* bpp = bp.p[L] + ((size_t)b * 36 + (size_t)a * 4) * (size_t)HW + pix;
    float ty = bpp[0];
    float tx = bpp[HW];
    float th = bpp[2 * HW];
    float tw = bpp[3 * HW];

    float4 an = *(const float4*)(anchors + 4 * (size_t)n); // y1,x1,y2,x2
    float ya = __fmul_rn(__fadd_rn(an.x, an.z), 0.5f);
    float xa = __fmul_rn(__fadd_rn(an.y, an.w), 0.5f);
    float ha = __fsub_rn(an.z, an.x);
    float wa = __fsub_rn(an.w, an.y);
    float w  = __fmul_rn(__nv_expf(tw), wa);
    float h  = __fmul_rn(__nv_expf(th), ha);
    float yc = __fmaf_rn(ty, ha, ya);
    float xc = __fmaf_rn(tx, wa, xa);
    float x1 = __fmaf_rn(w, -0.5f, xc);
    float y1 = __fmaf_rn(h, -0.5f, yc);
    float x2 = __fmaf_rn(w,  0.5f, xc);
    float y2 = __fmaf_rn(h,  0.5f, yc);

    g_x1[b][k] = x1; g_y1[b][k] = y1; g_x2[b][k] = x2; g_y2[b][k] = y2;
    g_sc[b][k] = score;
    g_cl[b][k] = (float)c;
}

// ---------------- NMS body (shared by hot kernel and fallback) ----------------
__device__ __forceinline__ void nms_body(int b, int t, float* out,
                                         float* sx1, float* sy1, float* sx2, float* sy2, float* scl,
                                         unsigned long long* red) {
    float S[FULL_E], X1[FULL_E], Y1[FULL_E], X2[FULL_E], Y2[FULL_E], AR[FULL_E];
    unsigned long long best = 0ull;
#pragma unroll
    for (int e = 0; e < FULL_E; e++) {
        int sl = e * FULL_T + t;
        float x1 = g_x1[b][sl], y1 = g_y1[b][sl], x2 = g_x2[b][sl], y2 = g_y2[b][sl];
        float s = g_sc[b][sl], cl = g_cl[b][sl];
        sx1[sl] = x1; sy1[sl] = y1; sx2[sl] = x2; sy2[sl] = y2; scl[sl] = cl;
        X1[e] = x1; Y1[e] = y1; X2[e] = x2; Y2[e] = y2; S[e] = s;
        AR[e] = __fmul_rn(__fsub_rn(x2, x1), __fsub_rn(y2, y1));
        unsigned kb = (s > 0.f) ? __float_as_uint(s) : 0u;
        best = umax64(best, ((unsigned long long)kb << 32) | (unsigned)(~sl));
    }
    __syncthreads();

    for (int it = 0; it < 100; it++) {
        unsigned long long v = best;
#pragma unroll
        for (int o = 16; o; o >>= 1) v = umax64(v, __shfl_down_sync(0xffffffffu, v, o));
        if ((t & 31) == 0) red[t >> 5] = v;
        __syncthreads();
        if (t < 32) {
            unsigned long long w = (t < 16) ? red[t] : 0ull;
#pragma unroll
            for (int o = 8; o; o >>= 1) w = umax64(w, __shfl_down_sync(0xffffffffu, w, o));
            if (t == 0) red[0] = w;
        }
        __syncthreads();
        unsigned long long ball = red[0];
        int slot = (int)(~(unsigned)ball);
        float ps = __uint_as_float((unsigned)(ball >> 32));
        float px1 = sx1[slot], py1 = sy1[slot], px2 = sx2[slot], py2 = sy2[slot];
        float pdx = __fsub_rn(px2, px1);
        float pdy = __fsub_rn(py2, py1);
        if (t == 0) {
            float* o = out + ((size_t)b * 100 + it) * 6;
            o[0] = px1; o[1] = py1; o[2] = px2; o[3] = py2; o[4] = ps; o[5] = scl[slot];
        }
        best = 0ull;
#pragma unroll
        for (int e = 0; e < FULL_E; e++) {
            int sl = e * FULL_T + t;
            float s = S[e];
            if (sl == slot) {
                s = -1.0f;
            } else if (s > 0.f) {
                float ix1 = fmaxf(px1, X1[e]);
                float iy1 = fmaxf(py1, Y1[e]);
                float ix2 = fminf(px2, X2[e]);
                float iy2 = fminf(py2, Y2[e]);
                float cw = __fsub_rn(ix2, ix1);
                float ch = __fsub_rn(iy2, iy1);
                if (cw > 0.f && ch > 0.f) {
                    float inter = __fmul_rn(cw, ch);
                    float t1 = __fmaf_rn(pdx, pdy, AR[e]);
                    float t2 = __fmaf_rn(-cw, ch, t1);
                    float den = __fadd_rn(t2, 1e-8f);
                    float iou = __fdiv_rn(inter, den);
                    float m2 = __fmul_rn(iou, iou);
                    float decay = __nv_expf(__fmul_rn(m2, -2.0f));
                    s = __fmul_rn(s, decay);
                }
            }
            S[e] = s;
            unsigned kb = (s > 0.f) ? __float_as_uint(s) : 0u;
            best = umax64(best, ((unsigned long long)kb << 32) | (unsigned)(~sl));
        }
        __syncthreads();
    }
}

// ---------------- L3: hot-path NMS (profiled launch #3) ----------------
__global__ void __launch_bounds__(FULL_T, 1) k_nms(float* __restrict__ out) {
    extern __shared__ float sm[];
    float* sx1 = sm;
    float* sy1 = sm + NSLOT;
    float* sx2 = sm + 2 * NSLOT;
    float* sy2 = sm + 3 * NSLOT;
    float* scl = sm + 4 * NSLOT;
    __shared__ unsigned long long red[16];
    nms_body(blockIdx.x, threadIdx.x, out, sx1, sy1, sx2, sy2, scl, red);
}

// ================= guarded fallback chain (early-exit when speculation valid) =================

__global__ void k_histF(Levels lv) {
    if (!g_fb) return;
    if (blockIdx.x == 0 && blockIdx.y == 0 && blockIdx.z == 0 && threadIdx.x < NIMG) {
        g_bndCnt[threadIdx.x] = 0; g_selCnt[threadIdx.x] = 0;   // no other block reads these here
    }
    __shared__ int h[4096];
    int t = threadIdx.x;
    for (int j = t; j < 4096; j += blockDim.x) h[j] = 0;
    __syncthreads();
    int L = blockIdx.z;
    int n4 = lv.n4[L];
    int b = blockIdx.y;
    const float4* p = ((const float4*)lv.cls[L]) + (size_t)b * (size_t)n4;
    for (int i = blockIdx.x * blockDim.x + t; i < n4; i += gridDim.x * blockDim.x) {
        float4 v = p[i];
        atomicAdd(&h[f2k(v.x) >> 20], 1);
        atomicAdd(&h[f2k(v.y) >> 20], 1);
        atomicAdd(&h[f2k(v.z) >> 20], 1);
        atomicAdd(&h[f2k(v.w) >> 20], 1);
    }
    __syncthreads();
    for (int j = t; j < 4096; j += blockDim.x) {
        int c = h[j];
        if (c) atomicAdd(&g_hist[b][j], c);
    }
}

__global__ void k_bucketF() {
    if (!g_fb) return;
    int b = blockIdx.x, t = threadIdx.x;
    __shared__ int ps[256];
    int s = 0;
#pragma unroll
    for (int j = 0; j < 16; j++) s += g_hist[b][t * 16 + j];
    ps[t] = s;
    __syncthreads();
    if (t == 0) {
        int cum = 0, grp = -1;
        for (int g = 255; g >= 0; g--) {
            if (cum + ps[g] >= KTOP) { grp = g; break; }
            cum += ps[g];
        }
        int bucket = grp * 16;
        for (int j = 15; j >= 0; j--) {
            int bin = grp * 16 + j;
            int c = g_hist[b][bin];
            if (cum + c >= KTOP) { bucket = bin; break; }
            cum += c;
        }
        g_bucket[b] = bucket;
        g_cntAbove[b] = cum;
    }
}

__global__ void k_compactF(Levels lv) {
    if (!g_fb) return;
    int L = blockIdx.z;
    int n4 = lv.n4[L];
    int b = blockIdx.y;
    unsigned bucket = (unsigned)g_bucket[b];
    const float4* p = ((const float4*)lv.cls[L]) + (size_t)b * (size_t)n4;
    int hwlog = lv.hwlog[L];
    int hwmask = (1 << hwlog) - 1;
    int aoff = lv.aoff[L];
    for (int i = blockIdx.x * blockDim.x + threadIdx.x; i < n4; i += gridDim.x * blockDim.x) {
        float4 v = p[i];
        float vv[4] = { v.x, v.y, v.z, v.w };
#pragma unroll
        for (int j = 0; j < 4; j++) {
            unsigned kk = f2k(vv[j]);
            unsigned bin = kk >> 20;
            if (bin >= bucket) {
                int e = i * 4 + j;
                int ch = e >> hwlog;
                int pix = e & hwmask;
                int a = ch / 90;
                int c = ch - a * 90;
                int n = aoff + pix * 9 + a;
                unsigned fidx = (unsigned)(n * 90 + c);
                unsigned long long rec = ((unsigned long long)kk << 32) | fidx;
                if (bin > bucket) {
                    int pos = atomicAdd(&g_selCnt[b], 1);
                    if (pos < KTOP) g_sel[b][pos] = rec;
                } else {
                    int pos = atomicAdd(&g_bndCnt[b], 1);
                    if (pos < BND_CAP) g_bnd[b][pos] = rec;
                }
            }
        }
    }
}

__global__ void k_refineF() {
    if (!g_fb) return;
    int b = blockIdx.x, t = threadIdx.x; // 256 threads
    __shared__ int h2[4096];
    __shared__ int ps[256];
    __shared__ int s_f2, s_above2, s_cnt2, s_tcnt;
    __shared__ unsigned long long tl[TIE_CAP];

    int n = g_bndCnt[b]; if (n > BND_CAP) n = BND_CAP;
    int above = g_cntAbove[b];
    int need = KTOP - above;

    for (int i = t; i < 4096; i += 256) h2[i] = 0;
    __syncthreads();
    for (int i = t; i < n; i += 256) {
        unsigned long long rec = g_bnd[b][i];
        int bin = (int)((rec >> 40) & 0xFFFu);
        atomicAdd(&h2[bin], 1);
    }
    __syncthreads();
    {
        int s = 0;
#pragma unroll
        for (int j = 0; j < 16; j++) s += h2[t * 16 + j];
        ps[t] = s;
    }
    __syncthreads();
    if (t == 0) {
        int cum = 0, grp = -1;
        for (int g = 255; g >= 0; g--) {
            if (cum + ps[g] >= need) { grp = g; break; }
            cum += ps[g];
        }
        int f2 = grp * 16;
        for (int j = 15; j >= 0; j--) {
            int bin = grp * 16 + j;
            int c = h2[bin];
            if (cum + c >= need) { f2 = bin; break; }
            cum += c;
        }
        s_f2 = f2; s_above2 = cum; s_cnt2 = 0; s_tcnt = 0;
    }
    __syncthreads();
    int f2 = s_f2, above2 = s_above2;
    for (int i = t; i < n; i += 256) {
        unsigned long long rec = g_bnd[b][i];
        int bin = (int)((rec >> 40) & 0xFFFu);
        if (bin > f2) {
            int p = atomicAdd(&s_cnt2, 1);
            if (above + p < KTOP) g_sel[b][above + p] = rec;
        } else if (bin == f2) {
            int p = atomicAdd(&s_tcnt, 1);
            if (p < TIE_CAP) tl[p] = rec;
        }
    }
    __syncthreads();
    int m = s_tcnt; if (m > TIE_CAP) m = TIE_CAP;
    int need3 = need - above2;
    for (int i = t; i < m; i += 256) {
        unsigned long long ri = tl[i];
        unsigned ki = (unsigned)(ri >> 32);
        unsigned xi = (unsigned)ri;
        int rank = 0;
        for (int j = 0; j < m; j++) {
            unsigned long long rj = tl[j];
            unsigned kj = (unsigned)(rj >> 32);
            unsigned xj = (unsigned)rj;
            rank += (kj > ki) || (kj == ki && xj < xi);
        }
        if (rank < need3) {
            int pos = above + above2 + rank;
            if (pos < KTOP) g_sel[b][pos] = ri;
        }
    }
    // restore g_hist to zero for next replay (only dirtied on fallback path)
    __syncthreads();
    for (int i = t; i < 4096; i += 256) g_hist[b][i] = 0;
}

__global__ void __launch_bounds__(512, 1) k_sortF() {
    if (!g_fb) return;
    extern __shared__ unsigned long long sk[];
    int b = blockIdx.x, t = threadIdx.x;
    for (int i = t; i < NSORT; i += 512) {
        unsigned long long v = 0ull;
        if (i < KTOP) {
            unsigned long long rec = g_sel[b][i];
            v = (rec & 0xFFFFFFFF00000000ull) |
                (unsigned long long)(0xFFFFFFFFu - (unsigned)rec);
        }
        sk[i] = v;
    }
    __syncthreads();
    for (int k = 2; k <= NSORT; k <<= 1) {
        for (int j = k >> 1; j > 0; j >>= 1) {
            for (int i = t; i < NSORT; i += 512) {
                int l = i ^ j;
                if (l > i) {
                    unsigned long long a = sk[i], c = sk[l];
                    bool up = ((i & k) == 0);
                    if ((a > c) == up) { sk[i] = c; sk[l] = a; }
                }
            }
            __syncthreads();
        }
    }
    for (int r = t; r < KTOP; r += 512) {
        unsigned long long v = sk[NSORT - 1 - r];
        unsigned long long rec = (v & 0xFFFFFFFF00000000ull) |
                                 (unsigned long long)(0xFFFFFFFFu - (unsigned)v);
        g_sel[b][r] = rec;
    }
}

__global__ void k_decodeF(BoxPtrs bp, const float* __restrict__ anchors) {
    if (!g_fb) return;
    int b = blockIdx.y;
    int k = blockIdx.x * blockDim.x + threadIdx.x;
    if (k >= NSLOT) return;
    if (k >= KTOP) {
        g_x1[b][k] = 0.f; g_y1[b][k] = 0.f; g_x2[b][k] = 0.f; g_y2[b][k] = 0.f;
        g_sc[b][k] = -1.f; g_cl[b][k] = 0.f;
        return;
    }
    unsigned long long rec = g_sel[b][k];
    unsigned key = (unsigned)(rec >> 32);
    unsigned fidx = (unsigned)rec;
    if (fidx > MAXFIDX) fidx = 0;
    float v = k2f(key);
    float score = sigmoid_rn(v);

    int n = (int)(fidx / 90u);
    int c = (int)(fidx - (unsigned)n * 90u);

    int L, aoff, HW;
    if      (n < 36864) { L = 0; aoff = 0;     HW = 4096; }
    else if (n < 46080) { L = 1; aoff = 36864; HW = 1024; }
    else if (n < 48384) { L = 2; aoff = 46080; HW = 256;  }
    else if (n < 48960) { L = 3; aoff = 48384; HW = 64;   }
    else                { L = 4; aoff = 48960; HW = 16;   }
    int r = n - aoff;
    int pix = r / 9;
    int a = r - pix * 9;

    const float* bpp = bp.p[L] + ((size_t)b * 36 + (size_t)a * 4) * (size_t)HW + pix;
    float ty = bpp[0];
    float tx = bpp[HW];
    float th = bpp[2 * HW];
    float tw = bpp[3 * HW];

    float4 an = *(const float4*)(anchors + 4 * (size_t)n);
    float ya = __fmul_rn(__fadd_rn(an.x, an.z), 0.5f);
    float xa = __fmul_rn(__fadd_rn(an.y, an.w), 0.5f);
    float ha = __fsub_rn(an.z, an.x);
    float wa = __fsub_rn(an.w, an.y);
    float w  = __fmul_rn(__nv_expf(tw), wa);
    float h  = __fmul_rn(__nv_expf(th), ha);
    float yc = __fmaf_rn(ty, ha, ya);
    float xc = __fmaf_rn(tx, wa, xa);
    float x1 = __fmaf_rn(w, -0.5f, xc);
    float y1 = __fmaf_rn(h, -0.5f, yc);
    float x2 = __fmaf_rn(w,  0.5f, xc);
    float y2 = __fmaf_rn(h,  0.5f, yc);

    g_x1[b][k] = x1; g_y1[b][k] = y1; g_x2[b][k] = x2; g_y2[b][k] = y2;
    g_sc[b][k] = score;
    g_cl[b][k] = (float)c;
}

__global__ void __launch_bounds__(FULL_T, 1) k_nmsF(float* __restrict__ out) {
    int b = blockIdx.x, t = threadIdx.x;
    int fb = g_fb;                 // read before reset
    if (t == 0) g_bndCnt[b] = 0;   // replay-state reset (next replay's sweep needs 0)
    if (t == 1) g_selCnt[b] = 0;
    if (!fb) return;
    extern __shared__ float sm[];
    float* sx1 = sm;
    float* sy1 = sm + NSLOT;
    float* sx2 = sm + 2 * NSLOT;
    float* sy2 = sm + 3 * NSLOT;
    float* scl = sm + 4 * NSLOT;
    __shared__ unsigned long long red[16];
    nms_body(b, t, out, sx1, sy1, sx2, sy2, scl, red);
}

// ---------------- host ----------------
extern "C" void kernel_launch(void* const* d_in, const int* in_sizes, int n_in,
                              void* d_out, int out_size) {
    const float* cls[5] = { 0,0,0,0,0 };
    const float* box[5] = { 0,0,0,0,0 };
    const float* anchors = 0;
    for (int i = 0; i < n_in; i++) {
        const float* p = (const float*)d_in[i];
        switch (in_sizes[i]) {
            case 53084160: cls[0] = p; break;
            case 13271040: cls[1] = p; break;
            case 3317760:  cls[2] = p; break;
            case 829440:   cls[3] = p; break;
            case 207360:   cls[4] = p; break;
            case 2359296:  box[0] = p; break;
            case 589824:   box[1] = p; break;
            case 147456:   box[2] = p; break;
            case 36864:    box[3] = p; break;
            case 9216:     box[4] = p; break;
            case 196416:   anchors = p; break;
            default: break;
        }
    }
    static const int HW[5]    = { 4096, 1024, 256, 64, 16 };
    static const int HWLOG[5] = { 12, 10, 8, 6, 4 };
    static const int AOFF[5]  = { 0, 36864, 46080, 48384, 48960 };

    Levels lv;
    for (int L = 0; L < 5; L++) {
        lv.cls[L] = cls[L];
        lv.n4[L] = 810 * HW[L] / 4;
        lv.hwlog[L] = HWLOG[L];
        lv.aoff[L] = AOFF[L];
    }
    BoxPtrs bp;
    for (int L = 0; L < 5; L++) bp.p[L] = box[L];

    int nms_smem = 5 * NSLOT * (int)sizeof(float);
    int sel_smem = 2 * SEL_BINS * (int)sizeof(int);
    int sort_smem = NSORT * (int)sizeof(unsigned long long);
    cudaFuncSetAttribute(k_selectA, cudaFuncAttributeMaxDynamicSharedMemorySize, sel_smem);
    cudaFuncSetAttribute(k_nms, cudaFuncAttributeMaxDynamicSharedMemorySize, nms_smem);
    cudaFuncSetAttribute(k_sortF, cudaFuncAttributeMaxDynamicSharedMemorySize, sort_smem);
    cudaFuncSetAttribute(k_nmsF, cudaFuncAttributeMaxDynamicSharedMemorySize, nms_smem);

    // hot path (launch #3 = k_nms gets the ncu profile)
    k_sweep<<<dim3(256, NIMG, 5), 256>>>(lv);                    // 0
    k_selectA<<<NIMG, SEL_T, sel_smem>>>();                      // 1
    k_decode<<<dim3(NSLOT / 256, NIMG), 256>>>(bp, anchors);     // 2
    k_nms<<<NIMG, FULL_T, nms_smem>>>((float*)d_out);            // 3

    // guarded exact fallback
    k_histF<<<dim3(64, NIMG, 5), 256>>>(lv);                     // 4
    k_bucketF<<<NIMG, 256>>>();                                  // 5
    k_compactF<<<dim3(64, NIMG, 5), 256>>>(lv);                  // 6
    k_refineF<<<NIMG, 256>>>();                                  // 7
    k_sortF<<<NIMG, 512, sort_smem>>>();                         // 8
    k_decodeF<<<dim3(NSLOT / 256, NIMG), 256>>>(bp, anchors);    // 9
    k_nmsF<<<NIMG, FULL_T, nms_smem>>>((float*)d_out);           // 10
}

// round 15
// speedup vs baseline: 2.3549x; 2.3549x over previous
#include <cuda_runtime.h>
#include <cuda_bf16.h>
#include <math.h>

#define NIMG 16
#define KTOP 5000
#define NSLOT 5120          // 1024*5
#define BND_CAP 32768
#define TIE_CAP 512
#define NSORT 8192
#define SEL_BINS 16384
#define SEL_T 1024
#define SEL_BASE 0xC0400000u   // f2k(3.0f)
#define SEL_SHIFT 9
#define NMS_T 1024
#define NMS_E 5
#define FULL_T 512
#define FULL_E 10
#define MAXFIDX 4423679u

// libdevice precise exp (immune to -use_fast_math substitution)
extern "C" __device__ float __nv_expf(float);

// ---------------- device scratch (static, zero-initialized, no runtime alloc) ----------------
__device__ int   g_hist[NIMG][4096];
__device__ int   g_bucket[NIMG];
__device__ int   g_cntAbove[NIMG];
__device__ int   g_selCnt[NIMG];
__device__ int   g_bndCnt[NIMG];
__device__ int   g_fb;                      // selection fallback flag
__device__ unsigned long long g_sel[NIMG][KTOP];
__device__ unsigned long long g_bnd[NIMG][BND_CAP];

__device__ float g_x1[NIMG][NSLOT];
__device__ float g_y1[NIMG][NSLOT];
__device__ float g_x2[NIMG][NSLOT];
__device__ float g_y2[NIMG][NSLOT];
__device__ float g_sc[NIMG][NSLOT];
__device__ float g_cl[NIMG][NSLOT];

struct Levels {
    const float* cls[5];
    int n4[5];      // float4 per image
    int hwlog[5];
    int aoff[5];
};
struct BoxPtrs { const float* p[5]; };

// order-preserving float -> uint key (ascending)
__device__ __forceinline__ unsigned f2k(float f) {
    unsigned u = __float_as_uint(f);
    return (u & 0x80000000u) ? ~u : (u | 0x80000000u);
}
__device__ __forceinline__ float k2f(unsigned k) {
    return (k & 0x80000000u) ? __uint_as_float(k & 0x7FFFFFFFu) : __uint_as_float(~k);
}
__device__ __forceinline__ unsigned long long umax64(unsigned long long a, unsigned long long b) {
    return a > b ? a : b;
}
__device__ __forceinline__ float sigmoid_rn(float v) {
    return __fdiv_rn(1.0f, __fadd_rn(1.0f, __nv_expf(-v)));
}
// monotone (non-decreasing) bin over candidate keys; fine resolution near the
// top-5000 cutoff (z in [3.0, ~6.0]); below 3.0 -> bin 0, above -> clamped.
__device__ __forceinline__ unsigned selbin(unsigned kk) {
    if (kk < SEL_BASE) return 0u;
    unsigned d = (kk - SEL_BASE) >> SEL_SHIFT;
    return d > (SEL_BINS - 1) ? (SEL_BINS - 1) : d;
}

#define THRESH 2.6f

// ---------------- L0: fused single sweep — compact everything >= THRESH ----------------
__global__ void k_sweep(Levels lv) {
    if (blockIdx.x == 0 && blockIdx.y == 0 && blockIdx.z == 0 && threadIdx.x == 0) g_fb = 0;
    int L = blockIdx.z;
    int n4 = lv.n4[L];
    int b = blockIdx.y;
    const float4* p = ((const float4*)lv.cls[L]) + (size_t)b * (size_t)n4;
    int hwlog = lv.hwlog[L];
    int hwmask = (1 << hwlog) - 1;
    int aoff = lv.aoff[L];
    int stride = gridDim.x * blockDim.x;
    for (int i = blockIdx.x * blockDim.x + threadIdx.x; i < n4; i += stride) {
        float4 v = p[i];
        float mx = fmaxf(fmaxf(v.x, v.y), fmaxf(v.z, v.w));
        if (mx >= THRESH) {
            float vv[4] = { v.x, v.y, v.z, v.w };
#pragma unroll
            for (int j = 0; j < 4; j++) {
                if (vv[j] >= THRESH) {
                    int e = i * 4 + j;
                    int ch = e >> hwlog;
                    int pix = e & hwmask;
                    int a = ch / 90;
                    int c = ch - a * 90;
                    int n = aoff + pix * 9 + a;
                    unsigned fidx = (unsigned)(n * 90 + c);
                    unsigned long long rec = ((unsigned long long)f2k(vv[j]) << 32) | fidx;
                    int pos = atomicAdd(&g_bndCnt[b], 1);
                    if (pos < BND_CAP) g_bnd[b][pos] = rec;
                }
            }
        }
    }
}

// ---------------- L1: exact rank-ordered top-KTOP from candidates ----------------
__global__ void __launch_bounds__(SEL_T, 1) k_selectA() {
    extern __shared__ int sh[];                // h[SEL_BINS] | pfx[SEL_BINS]
    int* h = sh;
    int* pfx = sh + SEL_BINS;
    __shared__ unsigned long long tl[TIE_CAP];
    __shared__ int s_f, s_above, s_tcnt;
    __shared__ int wsum[32];

    int b = blockIdx.x, t = threadIdx.x;
    int n = g_bndCnt[b];
    if (n < KTOP || n > BND_CAP) {             // speculation failed for this image
        if (t == 0) atomicExch(&g_fb, 1);
        return;
    }
    if (t == 0) s_tcnt = 0;

    for (int i = t; i < SEL_BINS; i += SEL_T) h[i] = 0;
    __syncthreads();
    for (int i = t; i < n; i += SEL_T) {
        unsigned kk = (unsigned)(g_bnd[b][i] >> 32);
        atomicAdd(&h[selbin(kk)], 1);
    }
    __syncthreads();

    const int SPT = SEL_BINS / SEL_T;          // 16
    int base = t * SPT;
    int hv[SPT];
    int seg = 0;
#pragma unroll
    for (int j = 0; j < SPT; j++) { hv[j] = h[base + j]; seg += hv[j]; }
    int lane = t & 31, wid = t >> 5;
    int incl = seg;
#pragma unroll
    for (int o = 1; o < 32; o <<= 1) { int x = __shfl_up_sync(~0u, incl, o); if (lane >= o) incl += x; }
    if (lane == 31) wsum[wid] = incl;
    __syncthreads();
    if (wid == 0) {
        int v = wsum[lane];
#pragma unroll
        for (int o = 1; o < 32; o <<= 1) { int x = __shfl_up_sync(~0u, v, o); if (lane >= o) v += x; }
        wsum[lane] = v;
    }
    __syncthreads();
    int P = incl - seg + (wid ? wsum[wid - 1] : 0);   // exclusive prefix over threads
    int total = wsum[31];
    int suffix = total - P - seg;                     // sum over threads > t (higher bins)
    int run = suffix;
    int tp[SPT];
#pragma unroll
    for (int j = SPT - 1; j >= 0; j--) { tp[j] = run; run += hv[j]; }
#pragma unroll
    for (int j = 0; j < SPT; j++) {
        pfx[base + j] = tp[j];
        if (tp[j] < KTOP && tp[j] + hv[j] >= KTOP) { s_f = base + j; s_above = tp[j]; }
    }
    __syncthreads();
    int f = s_f, above = s_above;

    for (int i = t; i < n; i += SEL_T) {
        unsigned long long rec = g_bnd[b][i];
        int bin = (int)selbin((unsigned)(rec >> 32));
        if (bin > f) {
            int p = atomicAdd(&pfx[bin], 1);
            g_sel[b][p] = rec;
        } else if (bin == f) {
            int p = atomicAdd(&s_tcnt, 1);
            if (p < TIE_CAP) tl[p] = rec;
        }
    }
    __syncthreads();
    int m = s_tcnt;
    if (m > TIE_CAP) {
        if (t == 0) atomicExch(&g_fb, 1);
        return;
    }
    int need = KTOP - above;
    for (int i = t; i < m; i += SEL_T) {
        unsigned long long ri = tl[i];
        unsigned ki = (unsigned)(ri >> 32);
        unsigned xi = (unsigned)ri;
        int rank = 0;
        for (int j = 0; j < m; j++) {
            unsigned long long rj = tl[j];
            unsigned kj = (unsigned)(rj >> 32);
            unsigned xj = (unsigned)rj;
            rank += (kj > ki) || (kj == ki && xj < xi);
        }
        if (rank < need) g_sel[b][above + rank] = ri;
    }
    __syncthreads();

    // fixup: bins above threshold with >1 record need within-bin ordering (key desc, fidx asc)
#pragma unroll
    for (int j = 0; j < SPT; j++) {
        int bin = base + j;
        if (bin > f) {
            int cnt = hv[j];
            if (cnt > 1) {
                if (cnt > 32) { atomicExch(&g_fb, 1); continue; }
                int st = pfx[bin] - cnt;
                unsigned long long v[32];
                for (int q = 0; q < cnt; q++) {
                    unsigned long long r = g_sel[b][st + q];
                    v[q] = (r & 0xFFFFFFFF00000000ull) | (unsigned long long)(0xFFFFFFFFu - (unsigned)r);
                }
                for (int a = 1; a < cnt; a++) {
                    unsigned long long x = v[a];
                    int c = a - 1;
                    while (c >= 0 && v[c] < x) { v[c + 1] = v[c]; c--; }
                    v[c + 1] = x;
                }
                for (int q = 0; q < cnt; q++) {
                    unsigned long long x = v[q];
                    g_sel[b][st + q] = (x & 0xFFFFFFFF00000000ull) | (unsigned long long)(0xFFFFFFFFu - (unsigned)x);
                }
            }
        }
    }
}

// ---------------- L2: decode (parallel, garbage-safe when speculation failed) ----------------
__global__ void k_decode(BoxPtrs bp, const float* __restrict__ anchors) {
    int b = blockIdx.y;
    int k = blockIdx.x * blockDim.x + threadIdx.x;
    if (k >= NSLOT) return;
    if (k >= KTOP) {
        g_x1[b][k] = 0.f; g_y1[b][k] = 0.f; g_x2[b][k] = 0.f; g_y2[b][k] = 0.f;
        g_sc[b][k] = -1.f; g_cl[b][k] = 0.f;
        return;
    }
    unsigned long long rec = g_sel[b][k];
    unsigned key = (unsigned)(rec >> 32);
    unsigned fidx = (unsigned)rec;
    if (fidx > MAXFIDX) fidx = 0;
    float v = k2f(key);
    float score = sigmoid_rn(v);

    int n = (int)(fidx / 90u);
    int c = (int)(fidx - (unsigned)n * 90u);

    int L, aoff, HW;
    if      (n < 36864) { L = 0; aoff = 0;     HW = 4096; }
    else if (n < 46080) { L = 1; aoff = 36864; HW = 1024; }
    else if (n < 48384) { L = 2; aoff = 46080; HW = 256;  }
    else if (n < 48960) { L = 3; aoff = 48384; HW = 64;   }
    else                { L = 4; aoff = 48960; HW = 16;   }
    int r = n - aoff;
    int pix = r / 9;
    int a = r - pix * 9;

    const float* bpp = bp.p[L] + ((size_t)b * 36 + (size_t)a * 4) * (size_t)HW + pix;
    float ty = bpp[0];
    float tx = bpp[HW];
    float th = bpp[2 * HW];
    float tw = bpp[3 * HW];

    float4 an = *(const float4*)(anchors + 4 * (size_t)n); // y1,x1,y2,x2
    float ya = __fmul_rn(__fadd_rn(an.x, an.z), 0.5f);
    float xa = __fmul_rn(__fadd_rn(an.y, an.w), 0.5f);
    float ha = __fsub_rn(an.z, an.x);
    float wa = __fsub_rn(an.w, an.y);
    float w  = __fmul_rn(__nv_expf(tw), wa);
    float h  = __fmul_rn(__nv_expf(th), ha);
    float yc = __fmaf_rn(ty, ha, ya);
    float xc = __fmaf_rn(tx, wa, xa);
    float x1 = __fmaf_rn(w, -0.5f, xc);
    float y1 = __fmaf_rn(h, -0.5f, yc);
    float x2 = __fmaf_rn(w,  0.5f, xc);
    float y2 = __fmaf_rn(h,  0.5f, yc);

    g_x1[b][k] = x1; g_y1[b][k] = y1; g_x2[b][k] = x2; g_y2[b][k] = y2;
    g_sc[b][k] = score;
    g_cl[b][k] = (float)c;
}

// ---------------- L3: hot-path NMS — 1024 threads x 5 elems (profiled launch #3) ----------------
__global__ void __launch_bounds__(NMS_T, 1) k_nms(float* __restrict__ out) {
    extern __shared__ float sm[];
    float* sx1 = sm;
    float* sy1 = sm + NSLOT;
    float* sx2 = sm + 2 * NSLOT;
    float* sy2 = sm + 3 * NSLOT;
    float* scl = sm + 4 * NSLOT;
    __shared__ unsigned long long red[32];

    int b = blockIdx.x, t = threadIdx.x;

    float S[NMS_E], X1[NMS_E], Y1[NMS_E], X2[NMS_E], Y2[NMS_E], AR[NMS_E];
    unsigned long long best = 0ull;
#pragma unroll
    for (int e = 0; e < NMS_E; e++) {
        int sl = e * NMS_T + t;
        float x1 = g_x1[b][sl], y1 = g_y1[b][sl], x2 = g_x2[b][sl], y2 = g_y2[b][sl];
        float s = g_sc[b][sl], cl = g_cl[b][sl];
        sx1[sl] = x1; sy1[sl] = y1; sx2[sl] = x2; sy2[sl] = y2; scl[sl] = cl;
        X1[e] = x1; Y1[e] = y1; X2[e] = x2; Y2[e] = y2; S[e] = s;
        AR[e] = __fmul_rn(__fsub_rn(x2, x1), __fsub_rn(y2, y1));
        unsigned kb = (s > 0.f) ? __float_as_uint(s) : 0u;
        best = umax64(best, ((unsigned long long)kb << 32) | (unsigned)(~sl));
    }
    __syncthreads();

    for (int it = 0; it < 100; it++) {
        unsigned long long v = best;
#pragma unroll
        for (int o = 16; o; o >>= 1) v = umax64(v, __shfl_down_sync(0xffffffffu, v, o));
        if ((t & 31) == 0) red[t >> 5] = v;
        __syncthreads();
        if (t < 32) {
            unsigned long long w = red[t];
#pragma unroll
            for (int o = 16; o; o >>= 1) w = umax64(w, __shfl_down_sync(0xffffffffu, w, o));
            if (t == 0) red[0] = w;
        }
        __syncthreads();
        unsigned long long ball = red[0];
        int slot = (int)(~(unsigned)ball);
        float ps = __uint_as_float((unsigned)(ball >> 32));
        float px1 = sx1[slot], py1 = sy1[slot], px2 = sx2[slot], py2 = sy2[slot];
        float pdx = __fsub_rn(px2, px1);
        float pdy = __fsub_rn(py2, py1);
        if (t == 0) {
            float* o = out + ((size_t)b * 100 + it) * 6;
            o[0] = px1; o[1] = py1; o[2] = px2; o[3] = py2; o[4] = ps; o[5] = scl[slot];
        }
        best = 0ull;
#pragma unroll
        for (int e = 0; e < NMS_E; e++) {
            int sl = e * NMS_T + t;
            float s = S[e];
            if (sl == slot) {
                s = -1.0f;
            } else if (s > 0.f) {
                float ix1 = fmaxf(px1, X1[e]);
                float iy1 = fmaxf(py1, Y1[e]);
                float ix2 = fminf(px2, X2[e]);
                float iy2 = fminf(py2, Y2[e]);
                float cw = __fsub_rn(ix2, ix1);
                float ch = __fsub_rn(iy2, iy1);
                if (cw > 0.f && ch > 0.f) {
                    float inter = __fmul_rn(cw, ch);
                    float t1 = __fmaf_rn(pdx, pdy, AR[e]);
                    float t2 = __fmaf_rn(-cw, ch, t1);
                    float den = __fadd_rn(t2, 1e-8f);
                    float iou = __fdiv_rn(inter, den);
                    float m2 = __fmul_rn(iou, iou);
                    float decay = __nv_expf(__fmul_rn(m2, -2.0f));
                    s = __fmul_rn(s, decay);
                }
            }
            S[e] = s;
            unsigned kb = (s > 0.f) ? __float_as_uint(s) : 0u;
            best = umax64(best, ((unsigned long long)kb << 32) | (unsigned)(~sl));
        }
        __syncthreads();
    }
}

// ================= guarded fallback chain (early-exit when speculation valid) =================

__global__ void k_histF(Levels lv) {
    if (!g_fb) return;
    if (blockIdx.x == 0 && blockIdx.y == 0 && blockIdx.z == 0 && threadIdx.x < NIMG) {
        g_bndCnt[threadIdx.x] = 0; g_selCnt[threadIdx.x] = 0;
    }
    __shared__ int h[4096];
    int t = threadIdx.x;
    for (int j = t; j < 4096; j += blockDim.x) h[j] = 0;
    __syncthreads();
    int L = blockIdx.z;
    int n4 = lv.n4[L];
    int b = blockIdx.y;
    const float4* p = ((const float4*)lv.cls[L]) + (size_t)b * (size_t)n4;
    for (int i = blockIdx.x * blockDim.x + t; i < n4; i += gridDim.x * blockDim.x) {
        float4 v = p[i];
        atomicAdd(&h[f2k(v.x) >> 20], 1);
        atomicAdd(&h[f2k(v.y) >> 20], 1);
        atomicAdd(&h[f2k(v.z) >> 20], 1);
        atomicAdd(&h[f2k(v.w) >> 20], 1);
    }
    __syncthreads();
    for (int j = t; j < 4096; j += blockDim.x) {
        int c = h[j];
        if (c) atomicAdd(&g_hist[b][j], c);
    }
}

__global__ void k_bucketF() {
    if (!g_fb) return;
    int b = blockIdx.x, t = threadIdx.x;
    __shared__ int ps[256];
    int s = 0;
#pragma unroll
    for (int j = 0; j < 16; j++) s += g_hist[b][t * 16 + j];
    ps[t] = s;
    __syncthreads();
    if (t == 0) {
        int cum = 0, grp = -1;
        for (int g = 255; g >= 0; g--) {
            if (cum + ps[g] >= KTOP) { grp = g; break; }
            cum += ps[g];
        }
        int bucket = grp * 16;
        for (int j = 15; j >= 0; j--) {
            int bin = grp * 16 + j;
            int c = g_hist[b][bin];
            if (cum + c >= KTOP) { bucket = bin; break; }
            cum += c;
        }
        g_bucket[b] = bucket;
        g_cntAbove[b] = cum;
    }
}

__global__ void k_compactF(Levels lv) {
    if (!g_fb) return;
    int L = blockIdx.z;
    int n4 = lv.n4[L];
    int b = blockIdx.y;
    unsigned bucket = (unsigned)g_bucket[b];
    const float4* p = ((const float4*)lv.cls[L]) + (size_t)b * (size_t)n4;
    int hwlog = lv.hwlog[L];
    int hwmask = (1 << hwlog) - 1;
    int aoff = lv.aoff[L];
    for (int i = blockIdx.x * blockDim.x + threadIdx.x; i < n4; i += gridDim.x * blockDim.x) {
        float4 v = p[i];
        float vv[4] = { v.x, v.y, v.z, v.w };
#pragma unroll
        for (int j = 0; j < 4; j++) {
            unsigned kk = f2k(vv[j]);
            unsigned bin = kk >> 20;
            if (bin >= bucket) {
                int e = i * 4 + j;
                int ch = e >> hwlog;
                int pix = e & hwmask;
                int a = ch / 90;
                int c = ch - a * 90;
                int n = aoff + pix * 9 + a;
                unsigned fidx = (unsigned)(n * 90 + c);
                unsigned long long rec = ((unsigned long long)kk << 32) | fidx;
                if (bin > bucket) {
                    int pos = atomicAdd(&g_selCnt[b], 1);
                    if (pos < KTOP) g_sel[b][pos] = rec;
                } else {
                    int pos = atomicAdd(&g_bndCnt[b], 1);
                    if (pos < BND_CAP) g_bnd[b][pos] = rec;
                }
            }
        }
    }
}

__global__ void k_refineF() {
    if (!g_fb) return;
    int b = blockIdx.x, t = threadIdx.x; // 256 threads
    __shared__ int h2[4096];
    __shared__ int ps[256];
    __shared__ int s_f2, s_above2, s_cnt2, s_tcnt;
    __shared__ unsigned long long tl[TIE_CAP];

    int n = g_bndCnt[b]; if (n > BND_CAP) n = BND_CAP;
    int above = g_cntAbove[b];
    int need = KTOP - above;

    for (int i = t; i < 4096; i += 256) h2[i] = 0;
    __syncthreads();
    for (int i = t; i < n; i += 256) {
        unsigned long long rec = g_bnd[b][i];
        int bin = (int)((rec >> 40) & 0xFFFu);
        atomicAdd(&h2[bin], 1);
    }
    __syncthreads();
    {
        int s = 0;
#pragma unroll
        for (int j = 0; j < 16; j++) s += h2[t * 16 + j];
        ps[t] = s;
    }
    __syncthreads();
    if (t == 0) {
        int cum = 0, grp = -1;
        for (int g = 255; g >= 0; g--) {
            if (cum + ps[g] >= need) { grp = g; break; }
            cum += ps[g];
        }
        int f2 = grp * 16;
        for (int j = 15; j >= 0; j--) {
            int bin = grp * 16 + j;
            int c = h2[bin];
            if (cum + c >= need) { f2 = bin; break; }
            cum += c;
        }
        s_f2 = f2; s_above2 = cum; s_cnt2 = 0; s_tcnt = 0;
    }
    __syncthreads();
    int f2 = s_f2, above2 = s_above2;
    for (int i = t; i < n; i += 256) {
        unsigned long long rec = g_bnd[b][i];
        int bin = (int)((rec >> 40) & 0xFFFu);
        if (bin > f2) {
            int p = atomicAdd(&s_cnt2, 1);
            if (above + p < KTOP) g_sel[b][above + p] = rec;
        } else if (bin == f2) {
            int p = atomicAdd(&s_tcnt, 1);
            if (p < TIE_CAP) tl[p] = rec;
        }
    }
    __syncthreads();
    int m = s_tcnt; if (m > TIE_CAP) m = TIE_CAP;
    int need3 = need - above2;
    for (int i = t; i < m; i += 256) {
        unsigned long long ri = tl[i];
        unsigned ki = (unsigned)(ri >> 32);
        unsigned xi = (unsigned)ri;
        int rank = 0;
        for (int j = 0; j < m; j++) {
            unsigned long long rj = tl[j];
            unsigned kj = (unsigned)(rj >> 32);
            unsigned xj = (unsigned)rj;
            rank += (kj > ki) || (kj == ki && xj < xi);
        }
        if (rank < need3) {
            int pos = above + above2 + rank;
            if (pos < KTOP) g_sel[b][pos] = ri;
        }
    }
    __syncthreads();
    for (int i = t; i < 4096; i += 256) g_hist[b][i] = 0;
}

__global__ void __launch_bounds__(512, 1) k_sortF() {
    if (!g_fb) return;
    extern __shared__ unsigned long long sk[];
    int b = blockIdx.x, t = threadIdx.x;
    for (int i = t; i < NSORT; i += 512) {
        unsigned long long v = 0ull;
        if (i < KTOP) {
            unsigned long long rec = g_sel[b][i];
            v = (rec & 0xFFFFFFFF00000000ull) |
                (unsigned long long)(0xFFFFFFFFu - (unsigned)rec);
        }
        sk[i] = v;
    }
    __syncthreads();
    for (int k = 2; k <= NSORT; k <<= 1) {
        for (int j = k >> 1; j > 0; j >>= 1) {
            for (int i = t; i < NSORT; i += 512) {
                int l = i ^ j;
                if (l > i) {
                    unsigned long long a = sk[i], c = sk[l];
                    bool up = ((i & k) == 0);
                    if ((a > c) == up) { sk[i] = c; sk[l] = a; }
                }
            }
            __syncthreads();
        }
    }
    for (int r = t; r < KTOP; r += 512) {
        unsigned long long v = sk[NSORT - 1 - r];
        unsigned long long rec = (v & 0xFFFFFFFF00000000ull) |
                                 (unsigned long long)(0xFFFFFFFFu - (unsigned)v);
        g_sel[b][r] = rec;
    }
}

__global__ void k_decodeF(BoxPtrs bp, const float* __restrict__ anchors) {
    if (!g_fb) return;
    int b = blockIdx.y;
    int k = blockIdx.x * blockDim.x + threadIdx.x;
    if (k >= NSLOT) return;
    if (k >= KTOP) {
        g_x1[b][k] = 0.f; g_y1[b][k] = 0.f; g_x2[b][k] = 0.f; g_y2[b][k] = 0.f;
        g_sc[b][k] = -1.f; g_cl[b][k] = 0.f;
        return;
    }
    unsigned long long rec = g_sel[b][k];
    unsigned key = (unsigned)(rec >> 32);
    unsigned fidx = (unsigned)rec;
    if (fidx > MAXFIDX) fidx = 0;
    float v = k2f(key);
    float score = sigmoid_rn(v);

    int n = (int)(fidx / 90u);
    int c = (int)(fidx - (unsigned)n * 90u);

    int L, aoff, HW;
    if      (n < 36864) { L = 0; aoff = 0;     HW = 4096; }
    else if (n < 46080) { L = 1; aoff = 36864; HW = 1024; }
    else if (n < 48384) { L = 2; aoff = 46080; HW = 256;  }
    else if (n < 48960) { L = 3; aoff = 48384; HW = 64;   }
    else                { L = 4; aoff = 48960; HW = 16;   }
    int r = n - aoff;
    int pix = r / 9;
    int a = r - pix * 9;

    const float* bpp = bp.p[L] + ((size_t)b * 36 + (size_t)a * 4) * (size_t)HW + pix;
    float ty = bpp[0];
    float tx = bpp[HW];
    float th = bpp[2 * HW];
    float tw = bpp[3 * HW];

    float4 an = *(const float4*)(anchors + 4 * (size_t)n);
    float ya = __fmul_rn(__fadd_rn(an.x, an.z), 0.5f);
    float xa = __fmul_rn(__fadd_rn(an.y, an.w), 0.5f);
    float ha = __fsub_rn(an.z, an.x);
    float wa = __fsub_rn(an.w, an.y);
    float w  = __fmul_rn(__nv_expf(tw), wa);
    float h  = __fmul_rn(__nv_expf(th), ha);
    float yc = __fmaf_rn(ty, ha, ya);
    float xc = __fmaf_rn(tx, wa, xa);
    float x1 = __fmaf_rn(w, -0.5f, xc);
    float y1 = __fmaf_rn(h, -0.5f, yc);
    float x2 = __fmaf_rn(w,  0.5f, xc);
    float y2 = __fmaf_rn(h,  0.5f, yc);

    g_x1[b][k] = x1; g_y1[b][k] = y1; g_x2[b][k] = x2; g_y2[b][k] = y2;
    g_sc[b][k] = score;
    g_cl[b][k] = (float)c;
}

__global__ void __launch_bounds__(FULL_T, 1) k_nmsF(float* __restrict__ out) {
    int b = blockIdx.x, t = threadIdx.x;
    int fb = g_fb;                 // read before reset
    if (t == 0) g_bndCnt[b] = 0;   // replay-state reset
    if (t == 1) g_selCnt[b] = 0;
    if (!fb) return;
    extern __shared__ float sm[];
    float* sx1 = sm;
    float* sy1 = sm + NSLOT;
    float* sx2 = sm + 2 * NSLOT;
    float* sy2 = sm + 3 * NSLOT;
    float* scl = sm + 4 * NSLOT;
    __shared__ unsigned long long red[16];

    float S[FULL_E], X1[FULL_E], Y1[FULL_E], X2[FULL_E], Y2[FULL_E], AR[FULL_E];
    unsigned long long best = 0ull;
#pragma unroll
    for (int e = 0; e < FULL_E; e++) {
        int sl = e * FULL_T + t;
        float x1 = g_x1[b][sl], y1 = g_y1[b][sl], x2 = g_x2[b][sl], y2 = g_y2[b][sl];
        float s = g_sc[b][sl], cl = g_cl[b][sl];
        sx1[sl] = x1; sy1[sl] = y1; sx2[sl] = x2; sy2[sl] = y2; scl[sl] = cl;
        X1[e] = x1; Y1[e] = y1; X2[e] = x2; Y2[e] = y2; S[e] = s;
        AR[e] = __fmul_rn(__fsub_rn(x2, x1), __fsub_rn(y2, y1));
        unsigned kb = (s > 0.f) ? __float_as_uint(s) : 0u;
        best = umax64(best, ((unsigned long long)kb << 32) | (unsigned)(~sl));
    }
    __syncthreads();

    for (int it = 0; it < 100; it++) {
        unsigned long long v = best;
#pragma unroll
        for (int o = 16; o; o >>= 1) v = umax64(v, __shfl_down_sync(0xffffffffu, v, o));
        if ((t & 31) == 0) red[t >> 5] = v;
        __syncthreads();
        if (t < 32) {
            unsigned long long w = (t < 16) ? red[t] : 0ull;
#pragma unroll
            for (int o = 8; o; o >>= 1) w = umax64(w, __shfl_down_sync(0xffffffffu, w, o));
            if (t == 0) red[0] = w;
        }
        __syncthreads();
        unsigned long long ball = red[0];
        int slot = (int)(~(unsigned)ball);
        float ps = __uint_as_float((unsigned)(ball >> 32));
        float px1 = sx1[slot], py1 = sy1[slot], px2 = sx2[slot], py2 = sy2[slot];
        float pdx = __fsub_rn(px2, px1);
        float pdy = __fsub_rn(py2, py1);
        if (t == 0) {
            float* o = out + ((size_t)b * 100 + it) * 6;
            o[0] = px1; o[1] = py1; o[2] = px2; o[3] = py2; o[4] = ps; o[5] = scl[slot];
        }
        best = 0ull;
#pragma unroll
        for (int e = 0; e < FULL_E; e++) {
            int sl = e * FULL_T + t;
            float s = S[e];
            if (sl == slot) {
                s = -1.0f;
            } else if (s > 0.f) {
                float ix1 = fmaxf(px1, X1[e]);
                float iy1 = fmaxf(py1, Y1[e]);
                float ix2 = fminf(px2, X2[e]);
                float iy2 = fminf(py2, Y2[e]);
                float cw = __fsub_rn(ix2, ix1);
                float ch = __fsub_rn(iy2, iy1);
                if (cw > 0.f && ch > 0.f) {
                    float inter = __fmul_rn(cw, ch);
                    float t1 = __fmaf_rn(pdx, pdy, AR[e]);
                    float t2 = __fmaf_rn(-cw, ch, t1);
                    float den = __fadd_rn(t2, 1e-8f);
                    float iou = __fdiv_rn(inter, den);
                    float m2 = __fmul_rn(iou, iou);
                    float decay = __nv_expf(__fmul_rn(m2, -2.0f));
                    s = __fmul_rn(s, decay);
                }
            }
            S[e] = s;
            unsigned kb = (s > 0.f) ? __float_as_uint(s) : 0u;
            best = umax64(best, ((unsigned long long)kb << 32) | (unsigned)(~sl));
        }
        __syncthreads();
    }
}

// ---------------- host ----------------
extern "C" void kernel_launch(void* const* d_in, const int* in_sizes, int n_in,
                              void* d_out, int out_size) {
    const float* cls[5] = { 0,0,0,0,0 };
    const float* box[5] = { 0,0,0,0,0 };
    const float* anchors = 0;
    for (int i = 0; i < n_in; i++) {
        const float* p = (const float*)d_in[i];
        switch (in_sizes[i]) {
            case 53084160: cls[0] = p; break;
            case 13271040: cls[1] = p; break;
            case 3317760:  cls[2] = p; break;
            case 829440:   cls[3] = p; break;
            case 207360:   cls[4] = p; break;
            case 2359296:  box[0] = p; break;
            case 589824:   box[1] = p; break;
            case 147456:   box[2] = p; break;
            case 36864:    box[3] = p; break;
            case 9216:     box[4] = p; break;
            case 196416:   anchors = p; break;
            default: break;
        }
    }
    static const int HW[5]    = { 4096, 1024, 256, 64, 16 };
    static const int HWLOG[5] = { 12, 10, 8, 6, 4 };
    static const int AOFF[5]  = { 0, 36864, 46080, 48384, 48960 };

    Levels lv;
    for (int L = 0; L < 5; L++) {
        lv.cls[L] = cls[L];
        lv.n4[L] = 810 * HW[L] / 4;
        lv.hwlog[L] = HWLOG[L];
        lv.aoff[L] = AOFF[L];
    }
    BoxPtrs bp;
    for (int L = 0; L < 5; L++) bp.p[L] = box[L];

    int nms_smem = 5 * NSLOT * (int)sizeof(float);
    int sel_smem = 2 * SEL_BINS * (int)sizeof(int);
    int sort_smem = NSORT * (int)sizeof(unsigned long long);
    cudaFuncSetAttribute(k_selectA, cudaFuncAttributeMaxDynamicSharedMemorySize, sel_smem);
    cudaFuncSetAttribute(k_nms, cudaFuncAttributeMaxDynamicSharedMemorySize, nms_smem);
    cudaFuncSetAttribute(k_sortF, cudaFuncAttributeMaxDynamicSharedMemorySize, sort_smem);
    cudaFuncSetAttribute(k_nmsF, cudaFuncAttributeMaxDynamicSharedMemorySize, nms_smem);

    // hot path (launch #3 = k_nms gets the ncu profile)
    k_sweep<<<dim3(256, NIMG, 5), 256>>>(lv);                    // 0
    k_selectA<<<NIMG, SEL_T, sel_smem>>>();                      // 1
    k_decode<<<dim3(NSLOT / 256, NIMG), 256>>>(bp, anchors);     // 2
    k_nms<<<NIMG, NMS_T, nms_smem>>>((float*)d_out);             // 3

    // guarded exact fallback
    k_histF<<<dim3(64, NIMG, 5), 256>>>(lv);                     // 4
    k_bucketF<<<NIMG, 256>>>();                                  // 5
    k_compactF<<<dim3(64, NIMG, 5), 256>>>(lv);                  // 6
    k_refineF<<<NIMG, 256>>>();                                  // 7
    k_sortF<<<NIMG, 512, sort_smem>>>();                         // 8
    k_decodeF<<<dim3(NSLOT / 256, NIMG), 256>>>(bp, anchors);    // 9
    k_nmsF<<<NIMG, FULL_T, nms_smem>>>((float*)d_out);           // 10
}

// round 17
// speedup vs baseline: 2.5663x; 1.0898x over previous
#include <cuda_runtime.h>
#include <cuda_bf16.h>
#include <math.h>

#define NIMG 16
#define KTOP 5000
#define NSLOT 5120          // 1024*5
#define BND_CAP 32768
#define TIE_CAP 512
#define NSORT 8192
#define SEL_BINS 16384
#define SEL_T 1024
#define SEL_BASE 0xC0400000u   // f2k(3.0f)
#define SEL_SHIFT 9
#define NMS_T 1024
#define NMS_E 5
#define FULL_T 512
#define FULL_E 10
#define MAXFIDX 4423679u

// libdevice precise exp (immune to -use_fast_math substitution)
extern "C" __device__ float __nv_expf(float);

// ---------------- device scratch (static, zero-initialized, no runtime alloc) ----------------
__device__ int   g_hist[NIMG][4096];
__device__ int   g_selCnt[NIMG];
__device__ int   g_bndCnt[NIMG];
__device__ int   g_fb;                      // selection fallback flag
__device__ unsigned long long g_sel[NIMG][KTOP];
__device__ unsigned long long g_bnd[NIMG][BND_CAP];

__device__ float g_x1[NIMG][NSLOT];
__device__ float g_y1[NIMG][NSLOT];
__device__ float g_x2[NIMG][NSLOT];
__device__ float g_y2[NIMG][NSLOT];
__device__ float g_sc[NIMG][NSLOT];
__device__ float g_cl[NIMG][NSLOT];

struct Levels {
    const float* cls[5];
    int n4[5];      // float4 per image
    int hwlog[5];
    int aoff[5];
};
struct BoxPtrs { const float* p[5]; };

// order-preserving float -> uint key (ascending)
__device__ __forceinline__ unsigned f2k(float f) {
    unsigned u = __float_as_uint(f);
    return (u & 0x80000000u) ? ~u : (u | 0x80000000u);
}
__device__ __forceinline__ float k2f(unsigned k) {
    return (k & 0x80000000u) ? __uint_as_float(k & 0x7FFFFFFFu) : __uint_as_float(~k);
}
__device__ __forceinline__ unsigned long long umax64(unsigned long long a, unsigned long long b) {
    return a > b ? a : b;
}
__device__ __forceinline__ float sigmoid_rn(float v) {
    return __fdiv_rn(1.0f, __fadd_rn(1.0f, __nv_expf(-v)));
}
// monotone (non-decreasing) bin over candidate keys; fine resolution near the
// top-5000 cutoff; below 3.0 -> bin 0, above ~6 -> clamped.
__device__ __forceinline__ unsigned selbin(unsigned kk) {
    if (kk < SEL_BASE) return 0u;
    unsigned d = (kk - SEL_BASE) >> SEL_SHIFT;
    return d > (SEL_BINS - 1) ? (SEL_BINS - 1) : d;
}

#define THRESH 2.6f

// ---------------- sweep body ----------------
__device__ __forceinline__ void sweep_level(const float* cls, int n4, int hwlog, int aoff, int b) {
    const float4* p = ((const float4*)cls) + (size_t)b * (size_t)n4;
    int hwmask = (1 << hwlog) - 1;
    int stride = gridDim.x * blockDim.x;
    for (int i = blockIdx.x * blockDim.x + threadIdx.x; i < n4; i += stride) {
        float4 v = p[i];
        float mx = fmaxf(fmaxf(v.x, v.y), fmaxf(v.z, v.w));
        if (mx >= THRESH) {
            float vv[4] = { v.x, v.y, v.z, v.w };
#pragma unroll
            for (int j = 0; j < 4; j++) {
                if (vv[j] >= THRESH) {
                    int e = i * 4 + j;
                    int ch = e >> hwlog;
                    int pix = e & hwmask;
                    int a = ch / 90;
                    int c = ch - a * 90;
                    int n = aoff + pix * 9 + a;
                    unsigned fidx = (unsigned)(n * 90 + c);
                    unsigned long long rec = ((unsigned long long)f2k(vv[j]) << 32) | fidx;
                    int pos = atomicAdd(&g_bndCnt[b], 1);
                    if (pos < BND_CAP) g_bnd[b][pos] = rec;
                }
            }
        }
    }
}

// L0: small levels 1..4
__global__ void k_sweepA(Levels lv) {
    int L = blockIdx.z + 1;
    sweep_level(lv.cls[L], lv.n4[L], lv.hwlog[L], lv.aoff[L], blockIdx.y);
}
// L1: reset flag
__global__ void k_reset() { if (threadIdx.x == 0) g_fb = 0; }
// L2: pad slots [KTOP, NSLOT)
__global__ void k_pad() {
    int i = blockIdx.x * blockDim.x + threadIdx.x;
    int npad = NSLOT - KTOP;
    int b = i / npad;
    if (b >= NIMG) return;
    int k = KTOP + (i - b * npad);
    g_x1[b][k] = 0.f; g_y1[b][k] = 0.f; g_x2[b][k] = 0.f; g_y2[b][k] = 0.f;
    g_sc[b][k] = -1.f; g_cl[b][k] = 0.f;
}
// L3: big level 0 (gets the ncu profile)
__global__ void k_sweepB(Levels lv) {
    sweep_level(lv.cls[0], lv.n4[0], lv.hwlog[0], lv.aoff[0], blockIdx.y);
}

// ---------------- L4: exact rank-ordered top-KTOP from candidates ----------------
__global__ void __launch_bounds__(SEL_T, 1) k_selectA() {
    extern __shared__ int sh[];                // h[SEL_BINS] | pfx[SEL_BINS]
    int* h = sh;
    int* pfx = sh + SEL_BINS;
    __shared__ unsigned long long tl[TIE_CAP];
    __shared__ int s_f, s_above, s_tcnt;
    __shared__ int wsum[32];

    int b = blockIdx.x, t = threadIdx.x;
    int n = g_bndCnt[b];
    if (n < KTOP || n > BND_CAP) {             // speculation failed for this image
        if (t == 0) atomicExch(&g_fb, 1);
        return;
    }
    if (t == 0) s_tcnt = 0;

    for (int i = t; i < SEL_BINS; i += SEL_T) h[i] = 0;
    __syncthreads();
    for (int i = t; i < n; i += SEL_T) {
        unsigned kk = (unsigned)(g_bnd[b][i] >> 32);
        atomicAdd(&h[selbin(kk)], 1);
    }
    __syncthreads();

    const int SPT = SEL_BINS / SEL_T;          // 16
    int base = t * SPT;
    int hv[SPT];
    int seg = 0;
#pragma unroll
    for (int j = 0; j < SPT; j++) { hv[j] = h[base + j]; seg += hv[j]; }
    int lane = t & 31, wid = t >> 5;
    int incl = seg;
#pragma unroll
    for (int o = 1; o < 32; o <<= 1) { int x = __shfl_up_sync(~0u, incl, o); if (lane >= o) incl += x; }
    if (lane == 31) wsum[wid] = incl;
    __syncthreads();
    if (wid == 0) {
        int v = wsum[lane];
#pragma unroll
        for (int o = 1; o < 32; o <<= 1) { int x = __shfl_up_sync(~0u, v, o); if (lane >= o) v += x; }
        wsum[lane] = v;
    }
    __syncthreads();
    int P = incl - seg + (wid ? wsum[wid - 1] : 0);   // exclusive prefix over threads
    int total = wsum[31];
    int suffix = total - P - seg;                     // sum over threads > t (higher bins)
    int run = suffix;
    int tp[SPT];
#pragma unroll
    for (int j = SPT - 1; j >= 0; j--) { tp[j] = run; run += hv[j]; }
#pragma unroll
    for (int j = 0; j < SPT; j++) {
        pfx[base + j] = tp[j];
        if (tp[j] < KTOP && tp[j] + hv[j] >= KTOP) { s_f = base + j; s_above = tp[j]; }
    }
    __syncthreads();
    int f = s_f, above = s_above;

    for (int i = t; i < n; i += SEL_T) {
        unsigned long long rec = g_bnd[b][i];
        int bin = (int)selbin((unsigned)(rec >> 32));
        if (bin > f) {
            int p = atomicAdd(&pfx[bin], 1);
            g_sel[b][p] = rec;
        } else if (bin == f) {
            int p = atomicAdd(&s_tcnt, 1);
            if (p < TIE_CAP) tl[p] = rec;
        }
    }
    __syncthreads();
    int m = s_tcnt;
    if (m > TIE_CAP) {
        if (t == 0) atomicExch(&g_fb, 1);
        return;
    }
    int need = KTOP - above;
    for (int i = t; i < m; i += SEL_T) {
        unsigned long long ri = tl[i];
        unsigned ki = (unsigned)(ri >> 32);
        unsigned xi = (unsigned)ri;
        int rank = 0;
        for (int j = 0; j < m; j++) {
            unsigned long long rj = tl[j];
            unsigned kj = (unsigned)(rj >> 32);
            unsigned xj = (unsigned)rj;
            rank += (kj > ki) || (kj == ki && xj < xi);
        }
        if (rank < need) g_sel[b][above + rank] = ri;
    }
    __syncthreads();

    // fixup: bins above threshold with >1 record need within-bin ordering (key desc, fidx asc)
#pragma unroll
    for (int j = 0; j < SPT; j++) {
        int bin = base + j;
        if (bin > f) {
            int cnt = hv[j];
            if (cnt > 1) {
                if (cnt > 32) { atomicExch(&g_fb, 1); continue; }
                int st = pfx[bin] - cnt;
                unsigned long long v[32];
                for (int q = 0; q < cnt; q++) {
                    unsigned long long r = g_sel[b][st + q];
                    v[q] = (r & 0xFFFFFFFF00000000ull) | (unsigned long long)(0xFFFFFFFFu - (unsigned)r);
                }
                for (int a = 1; a < cnt; a++) {
                    unsigned long long x = v[a];
                    int c = a - 1;
                    while (c >= 0 && v[c] < x) { v[c + 1] = v[c]; c--; }
                    v[c + 1] = x;
                }
                for (int q = 0; q < cnt; q++) {
                    unsigned long long x = v[q];
                    g_sel[b][st + q] = (x & 0xFFFFFFFF00000000ull) | (unsigned long long)(0xFFFFFFFFu - (unsigned)x);
                }
            }
        }
    }
}

// ---------------- decode body ----------------
__device__ __forceinline__ void decode_one(BoxPtrs bp, const float* anchors, int b, int k) {
    unsigned long long rec = g_sel[b][k];
    unsigned key = (unsigned)(rec >> 32);
    unsigned fidx = (unsigned)rec;
    if (fidx > MAXFIDX) fidx = 0;              // safety on speculative-garbage path
    float v = k2f(key);
    float score = sigmoid_rn(v);

    int n = (int)(fidx / 90u);
    int c = (int)(fidx - (unsigned)n * 90u);

    int L, aoff, HW;
    if      (n < 36864) { L = 0; aoff = 0;     HW = 4096; }
    else if (n < 46080) { L = 1; aoff = 36864; HW = 1024; }
    else if (n < 48384) { L = 2; aoff = 46080; HW = 256;  }
    else if (n < 48960) { L = 3; aoff = 48384; HW = 64;   }
    else                { L = 4; aoff = 48960; HW = 16;   }
    int r = n - aoff;
    int pix = r / 9;
    int a = r - pix * 9;

    const float* bpp = bp.p[L] + ((size_t)b * 36 + (size_t)a * 4) * (size_t)HW + pix;
    float ty = bpp[0];
    float tx = bpp[HW];
    float th = bpp[2 * HW];
    float tw = bpp[3 * HW];

    float4 an = *(const float4*)(anchors + 4 * (size_t)n); // y1,x1,y2,x2
    float ya = __fmul_rn(__fadd_rn(an.x, an.z), 0.5f);
    float xa = __fmul_rn(__fadd_rn(an.y, an.w), 0.5f);
    float ha = __fsub_rn(an.z, an.x);
    float wa = __fsub_rn(an.w, an.y);
    float w  = __fmul_rn(__nv_expf(tw), wa);
    float h  = __fmul_rn(__nv_expf(th), ha);
    float yc = __fmaf_rn(ty, ha, ya);
    float xc = __fmaf_rn(tx, wa, xa);
    float x1 = __fmaf_rn(w, -0.5f, xc);
    float y1 = __fmaf_rn(h, -0.5f, yc);
    float x2 = __fmaf_rn(w,  0.5f, xc);
    float y2 = __fmaf_rn(h,  0.5f, yc);

    g_x1[b][k] = x1; g_y1[b][k] = y1; g_x2[b][k] = x2; g_y2[b][k] = y2;
    g_sc[b][k] = score;
    g_cl[b][k] = (float)c;
}

// ---------------- L5: decode ----------------
__global__ void k_decode(BoxPtrs bp, const float* __restrict__ anchors) {
    int b = blockIdx.y;
    int k = blockIdx.x * blockDim.x + threadIdx.x;
    if (k >= KTOP) return;
    decode_one(bp, anchors, b, k);
}

// ---------------- L6: hot-path NMS — 2-barrier butterfly reduction ----------------
__global__ void __launch_bounds__(NMS_T, 1) k_nms(float* __restrict__ out) {
    extern __shared__ float sm[];
    float* sx1 = sm;
    float* sy1 = sm + NSLOT;
    float* sx2 = sm + 2 * NSLOT;
    float* sy2 = sm + 3 * NSLOT;
    float* scl = sm + 4 * NSLOT;
    __shared__ unsigned long long red[32];

    int b = blockIdx.x, t = threadIdx.x;
    int lane = t & 31, wid = t >> 5;

    float S[NMS_E], X1[NMS_E], Y1[NMS_E], X2[NMS_E], Y2[NMS_E], AR[NMS_E];
    unsigned long long best = 0ull;
#pragma unroll
    for (int e = 0; e < NMS_E; e++) {
        int sl = e * NMS_T + t;
        float x1 = g_x1[b][sl], y1 = g_y1[b][sl], x2 = g_x2[b][sl], y2 = g_y2[b][sl];
        float s = g_sc[b][sl], cl = g_cl[b][sl];
        sx1[sl] = x1; sy1[sl] = y1; sx2[sl] = x2; sy2[sl] = y2; scl[sl] = cl;
        X1[e] = x1; Y1[e] = y1; X2[e] = x2; Y2[e] = y2; S[e] = s;
        AR[e] = __fmul_rn(__fsub_rn(x2, x1), __fsub_rn(y2, y1));
        unsigned kb = (s > 0.f) ? __float_as_uint(s) : 0u;
        best = umax64(best, ((unsigned long long)kb << 32) | (unsigned)(~sl));
    }
    __syncthreads();

    for (int it = 0; it < 100; it++) {
        // warp-level reduce (max is assoc/comm over packed u64 -> shape-invariant result)
        unsigned long long v = best;
#pragma unroll
        for (int o = 16; o; o >>= 1) v = umax64(v, __shfl_down_sync(0xffffffffu, v, o));
        if (lane == 0) red[wid] = v;
        __syncthreads();
        // every warp butterfly-reduces the 32 partials -> all threads get ball
        unsigned long long w = red[lane];
#pragma unroll
        for (int o = 16; o; o >>= 1) w = umax64(w, __shfl_xor_sync(0xffffffffu, w, o));
        unsigned long long ball = w;

        int slot = (int)(~(unsigned)ball);
        float ps = __uint_as_float((unsigned)(ball >> 32));
        float px1 = sx1[slot], py1 = sy1[slot], px2 = sx2[slot], py2 = sy2[slot];
        float pdx = __fsub_rn(px2, px1);
        float pdy = __fsub_rn(py2, py1);
        if (t == 0) {
            float* o = out + ((size_t)b * 100 + it) * 6;
            o[0] = px1; o[1] = py1; o[2] = px2; o[3] = py2; o[4] = ps; o[5] = scl[slot];
        }
        best = 0ull;
#pragma unroll
        for (int e = 0; e < NMS_E; e++) {
            int sl = e * NMS_T + t;
            float s = S[e];
            if (sl == slot) {
                s = -1.0f;
            } else if (s > 0.f) {
                float ix1 = fmaxf(px1, X1[e]);
                float iy1 = fmaxf(py1, Y1[e]);
                float ix2 = fminf(px2, X2[e]);
                float iy2 = fminf(py2, Y2[e]);
                float cw = __fsub_rn(ix2, ix1);
                float ch = __fsub_rn(iy2, iy1);
                if (cw > 0.f && ch > 0.f) {
                    float inter = __fmul_rn(cw, ch);
                    float t1 = __fmaf_rn(pdx, pdy, AR[e]);
                    float t2 = __fmaf_rn(-cw, ch, t1);
                    float den = __fadd_rn(t2, 1e-8f);
                    float iou = __fdiv_rn(inter, den);
                    float m2 = __fmul_rn(iou, iou);
                    float decay = __nv_expf(__fmul_rn(m2, -2.0f));
                    s = __fmul_rn(s, decay);
                }
            }
            S[e] = s;
            unsigned kb = (s > 0.f) ? __float_as_uint(s) : 0u;
            best = umax64(best, ((unsigned long long)kb << 32) | (unsigned)(~sl));
        }
        __syncthreads();   // protects red[] rewrite next iteration
    }
}

// ================= guarded fallback chain (early-exit when speculation valid) =================

__global__ void k_histF(Levels lv) {
    if (!g_fb) return;
    if (blockIdx.x == 0 && blockIdx.y == 0 && blockIdx.z == 0 && threadIdx.x < NIMG) {
        g_bndCnt[threadIdx.x] = 0; g_selCnt[threadIdx.x] = 0;
    }
    __shared__ int h[4096];
    int t = threadIdx.x;
    for (int j = t; j < 4096; j += blockDim.x) h[j] = 0;
    __syncthreads();
    int L = blockIdx.z;
    int n4 = lv.n4[L];
    int b = blockIdx.y;
    const float4* p = ((const float4*)lv.cls[L]) + (size_t)b * (size_t)n4;
    for (int i = blockIdx.x * blockDim.x + t; i < n4; i += gridDim.x * blockDim.x) {
        float4 v = p[i];
        atomicAdd(&h[f2k(v.x) >> 20], 1);
        atomicAdd(&h[f2k(v.y) >> 20], 1);
        atomicAdd(&h[f2k(v.z) >> 20], 1);
        atomicAdd(&h[f2k(v.w) >> 20], 1);
    }
    __syncthreads();
    for (int j = t; j < 4096; j += blockDim.x) {
        int c = h[j];
        if (c) atomicAdd(&g_hist[b][j], c);
    }
}

// compute 12-bit threshold bucket + count strictly above, from g_hist (256 threads)
__device__ __forceinline__ void calc_bucket(int b, int t, int* ps, int* s_bucket, int* s_above) {
    int s = 0;
#pragma unroll
    for (int j = 0; j < 16; j++) s += g_hist[b][t * 16 + j];
    ps[t] = s;
    __syncthreads();
    if (t == 0) {
        int cum = 0, grp = -1;
        for (int g = 255; g >= 0; g--) {
            if (cum + ps[g] >= KTOP) { grp = g; break; }
            cum += ps[g];
        }
        int bucket = grp * 16;
        for (int j = 15; j >= 0; j--) {
            int bin = grp * 16 + j;
            int c = g_hist[b][bin];
            if (cum + c >= KTOP) { bucket = bin; break; }
            cum += c;
        }
        *s_bucket = bucket;
        *s_above = cum;
    }
    __syncthreads();
}

__global__ void k_compactF(Levels lv) {
    if (!g_fb) return;
    __shared__ int ps[256];
    __shared__ int s_bucket, s_above;
    int t = threadIdx.x;
    int b = blockIdx.y;
    calc_bucket(b, t, ps, &s_bucket, &s_above);
    unsigned bucket = (unsigned)s_bucket;

    int L = blockIdx.z;
    int n4 = lv.n4[L];
    const float4* p = ((const float4*)lv.cls[L]) + (size_t)b * (size_t)n4;
    int hwlog = lv.hwlog[L];
    int hwmask = (1 << hwlog) - 1;
    int aoff = lv.aoff[L];
    for (int i = blockIdx.x * blockDim.x + t; i < n4; i += gridDim.x * blockDim.x) {
        float4 v = p[i];
        float vv[4] = { v.x, v.y, v.z, v.w };
#pragma unroll
        for (int j = 0; j < 4; j++) {
            unsigned kk = f2k(vv[j]);
            unsigned bin = kk >> 20;
            if (bin >= bucket) {
                int e = i * 4 + j;
                int ch = e >> hwlog;
                int pix = e & hwmask;
                int a = ch / 90;
                int c = ch - a * 90;
                int n = aoff + pix * 9 + a;
                unsigned fidx = (unsigned)(n * 90 + c);
                unsigned long long rec = ((unsigned long long)kk << 32) | fidx;
                if (bin > bucket) {
                    int pos = atomicAdd(&g_selCnt[b], 1);
                    if (pos < KTOP) g_sel[b][pos] = rec;
                } else {
                    int pos = atomicAdd(&g_bndCnt[b], 1);
                    if (pos < BND_CAP) g_bnd[b][pos] = rec;
                }
            }
        }
    }
}

__global__ void k_refineF() {
    if (!g_fb) return;
    int b = blockIdx.x, t = threadIdx.x; // 256 threads
    __shared__ int h2[4096];
    __shared__ int ps[256];
    __shared__ int s_bucket, s_aboveB;
    __shared__ int s_f2, s_above2, s_cnt2, s_tcnt;
    __shared__ unsigned long long tl[TIE_CAP];

    calc_bucket(b, t, ps, &s_bucket, &s_aboveB);
    int above = s_aboveB;

    int n = g_bndCnt[b]; if (n > BND_CAP) n = BND_CAP;
    int need = KTOP - above;

    for (int i = t; i < 4096; i += 256) h2[i] = 0;
    __syncthreads();
    for (int i = t; i < n; i += 256) {
        unsigned long long rec = g_bnd[b][i];
        int bin = (int)((rec >> 40) & 0xFFFu);
        atomicAdd(&h2[bin], 1);
    }
    __syncthreads();
    {
        int s = 0;
#pragma unroll
        for (int j = 0; j < 16; j++) s += h2[t * 16 + j];
        ps[t] = s;
    }
    __syncthreads();
    if (t == 0) {
        int cum = 0, grp = -1;
        for (int g = 255; g >= 0; g--) {
            if (cum + ps[g] >= need) { grp = g; break; }
            cum += ps[g];
        }
        int f2 = grp * 16;
        for (int j = 15; j >= 0; j--) {
            int bin = grp * 16 + j;
            int c = h2[bin];
            if (cum + c >= need) { f2 = bin; break; }
            cum += c;
        }
        s_f2 = f2; s_above2 = cum; s_cnt2 = 0; s_tcnt = 0;
    }
    __syncthreads();
    int f2 = s_f2, above2 = s_above2;
    for (int i = t; i < n; i += 256) {
        unsigned long long rec = g_bnd[b][i];
        int bin = (int)((rec >> 40) & 0xFFFu);
        if (bin > f2) {
            int p = atomicAdd(&s_cnt2, 1);
            if (above + p < KTOP) g_sel[b][above + p] = rec;
        } else if (bin == f2) {
            int p = atomicAdd(&s_tcnt, 1);
            if (p < TIE_CAP) tl[p] = rec;
        }
    }
    __syncthreads();
    int m = s_tcnt; if (m > TIE_CAP) m = TIE_CAP;
    int need3 = need - above2;
    for (int i = t; i < m; i += 256) {
        unsigned long long ri = tl[i];
        unsigned ki = (unsigned)(ri >> 32);
        unsigned xi = (unsigned)ri;
        int rank = 0;
        for (int j = 0; j < m; j++) {
            unsigned long long rj = tl[j];
            unsigned kj = (unsigned)(rj >> 32);
            unsigned xj = (unsigned)rj;
            rank += (kj > ki) || (kj == ki && xj < xi);
        }
        if (rank < need3) {
            int pos = above + above2 + rank;
            if (pos < KTOP) g_sel[b][pos] = ri;
        }
    }
    __syncthreads();
    for (int i = t; i < 4096; i += 256) g_hist[b][i] = 0;   // reset for next replay
}

// fallback: bitonic sort into exact top_k rank order + fused decode
__global__ void __launch_bounds__(512, 1) k_sortdecF(BoxPtrs bp, const float* __restrict__ anchors) {
    if (!g_fb) return;
    extern __shared__ unsigned long long sk[];
    int b = blockIdx.x, t = threadIdx.x;
    for (int i = t; i < NSORT; i += 512) {
        unsigned long long v = 0ull;
        if (i < KTOP) {
            unsigned long long rec = g_sel[b][i];
            v = (rec & 0xFFFFFFFF00000000ull) |
                (unsigned long long)(0xFFFFFFFFu - (unsigned)rec);
        }
        sk[i] = v;
    }
    __syncthreads();
    for (int k = 2; k <= NSORT; k <<= 1) {
        for (int j = k >> 1; j > 0; j >>= 1) {
            for (int i = t; i < NSORT; i += 512) {
                int l = i ^ j;
                if (l > i) {
                    unsigned long long a = sk[i], c = sk[l];
                    bool up = ((i & k) == 0);
                    if ((a > c) == up) { sk[i] = c; sk[l] = a; }
                }
            }
            __syncthreads();
        }
    }
    for (int r = t; r < KTOP; r += 512) {
        unsigned long long v = sk[NSORT - 1 - r];
        unsigned long long rec = (v & 0xFFFFFFFF00000000ull) |
                                 (unsigned long long)(0xFFFFFFFFu - (unsigned)v);
        g_sel[b][r] = rec;
    }
    __syncthreads();
    BoxPtrs bpl = bp;
    for (int k = t; k < KTOP; k += 512) decode_one(bpl, anchors, b, k);
}

__global__ void __launch_bounds__(FULL_T, 1) k_nmsF(float* __restrict__ out) {
    int b = blockIdx.x, t = threadIdx.x;
    int fb = g_fb;                 // read before reset
    if (t == 0) g_bndCnt[b] = 0;   // replay-state reset
    if (t == 1) g_selCnt[b] = 0;
    if (!fb) return;
    extern __shared__ float sm[];
    float* sx1 = sm;
    float* sy1 = sm + NSLOT;
    float* sx2 = sm + 2 * NSLOT;
    float* sy2 = sm + 3 * NSLOT;
    float* scl = sm + 4 * NSLOT;
    __shared__ unsigned long long red[16];

    float S[FULL_E], X1[FULL_E], Y1[FULL_E], X2[FULL_E], Y2[FULL_E], AR[FULL_E];
    unsigned long long best = 0ull;
#pragma unroll
    for (int e = 0; e < FULL_E; e++) {
        int sl = e * FULL_T + t;
        float x1 = g_x1[b][sl], y1 = g_y1[b][sl], x2 = g_x2[b][sl], y2 = g_y2[b][sl];
        float s = g_sc[b][sl], cl = g_cl[b][sl];
        sx1[sl] = x1; sy1[sl] = y1; sx2[sl] = x2; sy2[sl] = y2; scl[sl] = cl;
        X1[e] = x1; Y1[e] = y1; X2[e] = x2; Y2[e] = y2; S[e] = s;
        AR[e] = __fmul_rn(__fsub_rn(x2, x1), __fsub_rn(y2, y1));
        unsigned kb = (s > 0.f) ? __float_as_uint(s) : 0u;
        best = umax64(best, ((unsigned long long)kb << 32) | (unsigned)(~sl));
    }
    __syncthreads();

    for (int it = 0; it < 100; it++) {
        unsigned long long v = best;
#pragma unroll
        for (int o = 16; o; o >>= 1) v = umax64(v, __shfl_down_sync(0xffffffffu, v, o));
        if ((t & 31) == 0) red[t >> 5] = v;
        __syncthreads();
        if (t < 32) {
            unsigned long long w = (t < 16) ? red[t] : 0ull;
#pragma unroll
            for (int o = 8; o; o >>= 1) w = umax64(w, __shfl_down_sync(0xffffffffu, w, o));
            if (t == 0) red[0] = w;
        }
        __syncthreads();
        unsigned long long ball = red[0];
        int slot = (int)(~(unsigned)ball);
        float ps = __uint_as_float((unsigned)(ball >> 32));
        float px1 = sx1[slot], py1 = sy1[slot], px2 = sx2[slot], py2 = sy2[slot];
        float pdx = __fsub_rn(px2, px1);
        float pdy = __fsub_rn(py2, py1);
        if (t == 0) {
            float* o = out + ((size_t)b * 100 + it) * 6;
            o[0] = px1; o[1] = py1; o[2] = px2; o[3] = py2; o[4] = ps; o[5] = scl[slot];
        }
        best = 0ull;
#pragma unroll
        for (int e = 0; e < FULL_E; e++) {
            int sl = e * FULL_T + t;
            float s = S[e];
            if (sl == slot) {
                s = -1.0f;
            } else if (s > 0.f) {
                float ix1 = fmaxf(px1, X1[e]);
                float iy1 = fmaxf(py1, Y1[e]);
                float ix2 = fminf(px2, X2[e]);
                float iy2 = fminf(py2, Y2[e]);
                float cw = __fsub_rn(ix2, ix1);
                float ch = __fsub_rn(iy2, iy1);
                if (cw > 0.f && ch > 0.f) {
                    float inter = __fmul_rn(cw, ch);
                    float t1 = __fmaf_rn(pdx, pdy, AR[e]);
                    float t2 = __fmaf_rn(-cw, ch, t1);
                    float den = __fadd_rn(t2, 1e-8f);
                    float iou = __fdiv_rn(inter, den);
                    float m2 = __fmul_rn(iou, iou);
                    float decay = __nv_expf(__fmul_rn(m2, -2.0f));
                    s = __fmul_rn(s, decay);
                }
            }
            S[e] = s;
            unsigned kb = (s > 0.f) ? __float_as_uint(s) : 0u;
            best = umax64(best, ((unsigned long long)kb << 32) | (unsigned)(~sl));
        }
        __syncthreads();
    }
}

// ---------------- host ----------------
extern "C" void kernel_launch(void* const* d_in, const int* in_sizes, int n_in,
                              void* d_out, int out_size) {
    const float* cls[5] = { 0,0,0,0,0 };
    const float* box[5] = { 0,0,0,0,0 };
    const float* anchors = 0;
    for (int i = 0; i < n_in; i++) {
        const float* p = (const float*)d_in[i];
        switch (in_sizes[i]) {
            case 53084160: cls[0] = p; break;
            case 13271040: cls[1] = p; break;
            case 3317760:  cls[2] = p; break;
            case 829440:   cls[3] = p; break;
            case 207360:   cls[4] = p; break;
            case 2359296:  box[0] = p; break;
            case 589824:   box[1] = p; break;
            case 147456:   box[2] = p; break;
            case 36864:    box[3] = p; break;
            case 9216:     box[4] = p; break;
            case 196416:   anchors = p; break;
            default: break;
        }
    }
    static const int HW[5]    = { 4096, 1024, 256, 64, 16 };
    static const int HWLOG[5] = { 12, 10, 8, 6, 4 };
    static const int AOFF[5]  = { 0, 36864, 46080, 48384, 48960 };

    Levels lv;
    for (int L = 0; L < 5; L++) {
        lv.cls[L] = cls[L];
        lv.n4[L] = 810 * HW[L] / 4;
        lv.hwlog[L] = HWLOG[L];
        lv.aoff[L] = AOFF[L];
    }
    BoxPtrs bp;
    for (int L = 0; L < 5; L++) bp.p[L] = box[L];

    int nms_smem = 5 * NSLOT * (int)sizeof(float);
    int sel_smem = 2 * SEL_BINS * (int)sizeof(int);
    int sort_smem = NSORT * (int)sizeof(unsigned long long);
    cudaFuncSetAttribute(k_selectA, cudaFuncAttributeMaxDynamicSharedMemorySize, sel_smem);
    cudaFuncSetAttribute(k_nms, cudaFuncAttributeMaxDynamicSharedMemorySize, nms_smem);
    cudaFuncSetAttribute(k_sortdecF, cudaFuncAttributeMaxDynamicSharedMemorySize, sort_smem);
    cudaFuncSetAttribute(k_nmsF, cudaFuncAttributeMaxDynamicSharedMemorySize, nms_smem);

    // hot path (launch #3 = k_sweepB, the 212MB streaming pass, gets the ncu profile)
    k_sweepA<<<dim3(64, NIMG, 4), 256>>>(lv);                    // 0: levels 1-4
    k_reset<<<1, 32>>>();                                        // 1
    k_pad<<<(NIMG * (NSLOT - KTOP) + 255) / 256, 256>>>();       // 2
    k_sweepB<<<dim3(810, NIMG), 256>>>(lv);                      // 3: level 0 (profiled)
    k_selectA<<<NIMG, SEL_T, sel_smem>>>();                      // 4
    k_decode<<<dim3((KTOP + 255) / 256, NIMG), 256>>>(bp, anchors); // 5
    k_nms<<<NIMG, NMS_T, nms_smem>>>((float*)d_out);             // 6

    // guarded exact fallback
    k_histF<<<dim3(16, NIMG, 5), 256>>>(lv);                     // 7
    k_compactF<<<dim3(16, NIMG, 5), 256>>>(lv);                  // 8
    k_refineF<<<NIMG, 256>>>();                                  // 9
    k_sortdecF<<<NIMG, 512, sort_smem>>>(bp, anchors);           // 10
    k_nmsF<<<NIMG, FULL_T, nms_smem>>>((float*)d_out);           // 11
}